// round 11
// baseline (speedup 1.0000x reference)
#include <cuda_runtime.h>
#include <cuda_bf16.h>
#include <math.h>
#include <float.h>
#include <stdint.h>

// Problem constants
#define B_    2
#define T_    2048
#define DM_   2048
#define HQ_   32
#define HKV_  8
#define HD_   64
#define LOG2_THETA 13.287712379549449

// bf16 hi/lo split buffers (no allocs -> __device__ globals)
__device__ __nv_bfloat16 g_xhi[(size_t)4096 * 2048];
__device__ __nv_bfloat16 g_xlo[(size_t)4096 * 2048];
__device__ __nv_bfloat16 g_Whi[(size_t)3072 * 2048];   // WQ|WK|WV rows
__device__ __nv_bfloat16 g_Wlo[(size_t)3072 * 2048];
__device__ __nv_bfloat16 g_WOhi[(size_t)2048 * 2048];
__device__ __nv_bfloat16 g_WOlo[(size_t)2048 * 2048];
__device__ __nv_bfloat16 g_Ohi[(size_t)4096 * 2048];   // attention out
__device__ __nv_bfloat16 g_Olo[(size_t)4096 * 2048];
__device__ __nv_bfloat16 g_Qhi[(size_t)B_ * HQ_  * T_ * HD_];  // rope'd, pre-scaled
__device__ __nv_bfloat16 g_Qlo[(size_t)B_ * HQ_  * T_ * HD_];
__device__ __nv_bfloat16 g_Khi[(size_t)B_ * HKV_ * T_ * HD_];  // rope'd
__device__ __nv_bfloat16 g_Klo[(size_t)B_ * HKV_ * T_ * HD_];
__device__ __nv_bfloat16 g_Vhi[(size_t)B_ * HKV_ * T_ * HD_];
__device__ __nv_bfloat16 g_Vlo[(size_t)B_ * HKV_ * T_ * HD_];

// ============================================================================
// PTX helpers (legacy tensor path: plain PTX, valid on compute_103)
// ============================================================================
__device__ __forceinline__ uint32_t smem_u32(const void* p) {
    uint32_t a;
    asm("{ .reg .u64 t; cvta.to.shared.u64 t, %1; cvt.u32.u64 %0, t; }"
        : "=r"(a) : "l"(p));
    return a;
}
__device__ __forceinline__ void ldsm_x4(uint32_t& r0, uint32_t& r1,
                                        uint32_t& r2, uint32_t& r3, uint32_t a) {
    asm volatile("ldmatrix.sync.aligned.m8n8.x4.shared.b16 {%0,%1,%2,%3}, [%4];"
                 : "=r"(r0), "=r"(r1), "=r"(r2), "=r"(r3) : "r"(a));
}
__device__ __forceinline__ void ldsm_x4_t(uint32_t& r0, uint32_t& r1,
                                          uint32_t& r2, uint32_t& r3, uint32_t a) {
    asm volatile("ldmatrix.sync.aligned.m8n8.x4.trans.shared.b16 {%0,%1,%2,%3}, [%4];"
                 : "=r"(r0), "=r"(r1), "=r"(r2), "=r"(r3) : "r"(a));
}
__device__ __forceinline__ void mma16816(float* d, const uint32_t* a, const uint32_t* b) {
    asm volatile(
        "mma.sync.aligned.m16n8k16.row.col.f32.bf16.bf16.f32 "
        "{%0,%1,%2,%3}, {%4,%5,%6,%7}, {%8,%9}, {%0,%1,%2,%3};"
        : "+f"(d[0]), "+f"(d[1]), "+f"(d[2]), "+f"(d[3])
        : "r"(a[0]), "r"(a[1]), "r"(a[2]), "r"(a[3]), "r"(b[0]), "r"(b[1]));
}
__device__ __forceinline__ void split1(float v, __nv_bfloat16& h, __nv_bfloat16& l) {
    h = __float2bfloat16_rn(v);
    l = __float2bfloat16_rn(v - __bfloat162float(h));
}
__device__ __forceinline__ uint32_t pack_hl(float a, float b, uint32_t& lo) {
    __nv_bfloat16 ha, hb, la, lb;
    split1(a, ha, la);
    split1(b, hb, lb);
    lo = (uint32_t)__bfloat16_as_ushort(la) | ((uint32_t)__bfloat16_as_ushort(lb) << 16);
    return (uint32_t)__bfloat16_as_ushort(ha) | ((uint32_t)__bfloat16_as_ushort(hb) << 16);
}

// ============================================================================
// Kernel 0: fp32 -> (hi, lo) bf16 conversion for x, WQ|WK|WV, WO.
// ============================================================================
#define NE_X   8388608ull
#define NE_WQ  4194304ull
#define NE_WKV 1048576ull
#define CVT_TOTAL_F4 4718592

__global__ __launch_bounds__(256)
void cvt_kernel(const float* __restrict__ x,  const float* __restrict__ WQ,
                const float* __restrict__ WK, const float* __restrict__ WV,
                const float* __restrict__ WO)
{
    const size_t e = ((size_t)blockIdx.x * 256 + threadIdx.x) * 4;
    const float* src; __nv_bfloat16 *dh, *dl; size_t off;
    if (e < NE_X)                          { src = x;  dh = g_xhi;            dl = g_xlo;            off = e; }
    else if (e < NE_X + NE_WQ)             { src = WQ; dh = g_Whi;            dl = g_Wlo;            off = e - NE_X; }
    else if (e < NE_X + NE_WQ + NE_WKV)    { src = WK; dh = g_Whi + 4194304;  dl = g_Wlo + 4194304;  off = e - NE_X - NE_WQ; }
    else if (e < NE_X + NE_WQ + 2*NE_WKV)  { src = WV; dh = g_Whi + 5242880;  dl = g_Wlo + 5242880;  off = e - NE_X - NE_WQ - NE_WKV; }
    else                                   { src = WO; dh = g_WOhi;           dl = g_WOlo;           off = e - NE_X - NE_WQ - 2*NE_WKV; }
    float4 v = *(const float4*)(src + off);
    uint2 uh, ul;
    uh.x = pack_hl(v.x, v.y, ul.x);
    uh.y = pack_hl(v.z, v.w, ul.y);
    *(uint2*)(dh + off) = uh;
    *(uint2*)(dl + off) = ul;
}

// ============================================================================
// mma.sync split-fp32 GEMM:  D[256x128] = A * B^T, K=2048, BK=32.
// 256 thr = 8 warps (4m x 2n), warp tile 64x64 (mt=4) -> 85 B smem / MMA.
// Double-buffered smem, ONE barrier per chunk (LDG->STS into other buffer).
// MODE 0: QKV proj -> RoPE -> hi/lo bf16 Q/K/V (Q pre-scaled by 0.125).
// MODE 1: out proj -> fp32 to outp.
// ============================================================================
#define SPAD 40
#define AREG 10240                            // 256*SPAD bf16
#define BREG 5120                             // 128*SPAD bf16
#define BUF_ELEMS (2*AREG + 2*BREG)           // 30720 bf16 per buffer
#define GEMM_SMEM_BYTES (2 * BUF_ELEMS * 2)   // 122880 B

template <int MODE>
__global__ __launch_bounds__(256)
void gemm_mma_kernel(const int* __restrict__ pos, float* __restrict__ outp)
{
    extern __shared__ __align__(16) __nv_bfloat16 smg[];
    const uint32_t smBase = smem_u32(smg);

    const int j0 = blockIdx.x * 128;
    const int m0 = blockIdx.y * 256;
    const int tid = threadIdx.x;
    const int wid = tid >> 5, lane = tid & 31;

    const __nv_bfloat16* Ahi = (MODE == 0) ? g_xhi : g_Ohi;
    const __nv_bfloat16* Alo = (MODE == 0) ? g_xlo : g_Olo;
    const __nv_bfloat16* Bhi = ((MODE == 0) ? g_Whi : g_WOhi) + (size_t)j0 * DM_;
    const __nv_bfloat16* Blo = ((MODE == 0) ? g_Wlo : g_WOlo) + (size_t)j0 * DM_;

    const size_t aoff = (size_t)(m0 + tid) * DM_;        // A: one row per thread
    const int brow_ld = tid >> 1;                        // B: 2 threads per row
    const int bcol_ld = (tid & 1) * 16;
    const size_t boff = (size_t)brow_ld * DM_ + bcol_ld;

    const int wm = (wid & 3) * 64;
    const int wn = (wid >> 2) * 64;

    float acc[4][8][4];
#pragma unroll
    for (int mt = 0; mt < 4; mt++)
#pragma unroll
        for (int nt = 0; nt < 8; nt++)
#pragma unroll
            for (int q = 0; q < 4; q++) acc[mt][nt][q] = 0.f;

    // LDG -> STS chunk kc into buffer buf
    auto load_chunk = [&](int kc, int buf) {
        const size_t nk = (size_t)kc * 32;
        __nv_bfloat16* p = smg + (size_t)buf * BUF_ELEMS;
        const int as = tid * SPAD;
#pragma unroll
        for (int v = 0; v < 4; v++) {
            *(uint4*)&p[as + v * 8]        = *(const uint4*)(Ahi + aoff + nk + v * 8);
            *(uint4*)&p[AREG + as + v * 8] = *(const uint4*)(Alo + aoff + nk + v * 8);
        }
        const int bs = brow_ld * SPAD + bcol_ld;
        *(uint4*)&p[2 * AREG + bs]            = *(const uint4*)(Bhi + boff + nk);
        *(uint4*)&p[2 * AREG + bs + 8]        = *(const uint4*)(Bhi + boff + nk + 8);
        *(uint4*)&p[2 * AREG + BREG + bs]     = *(const uint4*)(Blo + boff + nk);
        *(uint4*)&p[2 * AREG + BREG + bs + 8] = *(const uint4*)(Blo + boff + nk + 8);
    };

    load_chunk(0, 0);
    __syncthreads();

    for (int kc = 0; kc < DM_ / 32; kc++) {
        if (kc + 1 < DM_ / 32) load_chunk(kc + 1, (kc + 1) & 1);

        const uint32_t bufB = smBase + (uint32_t)(kc & 1) * (BUF_ELEMS * 2);
        const uint32_t AhiB = bufB;
        const uint32_t AloB = bufB + AREG * 2;
        const uint32_t BhiB = bufB + 4 * AREG;
        const uint32_t BloB = BhiB + BREG * 2;

#pragma unroll
        for (int ks = 0; ks < 2; ks++) {
            uint32_t bh[8][2], bl[8][2];
            const int brow = wn + ((lane >> 4) & 1) * 8 + (lane & 7);
            const int bcol = ks * 16 + ((lane >> 3) & 1) * 8;
#pragma unroll
            for (int p = 0; p < 4; p++) {
                const uint32_t off = (uint32_t)((brow + p * 16) * SPAD + bcol) * 2u;
                ldsm_x4(bh[2*p][0], bh[2*p][1], bh[2*p+1][0], bh[2*p+1][1], BhiB + off);
                ldsm_x4(bl[2*p][0], bl[2*p][1], bl[2*p+1][0], bl[2*p+1][1], BloB + off);
            }
            const int arow = wm + (lane & 15);
            const int acol = ks * 16 + (lane >> 4) * 8;
#pragma unroll
            for (int mt = 0; mt < 4; mt++) {
                uint32_t ah[4], al[4];
                const uint32_t off = (uint32_t)((arow + mt * 16) * SPAD + acol) * 2u;
                ldsm_x4(ah[0], ah[1], ah[2], ah[3], AhiB + off);
                ldsm_x4(al[0], al[1], al[2], al[3], AloB + off);
#pragma unroll
                for (int nt = 0; nt < 8; nt++) mma16816(acc[mt][nt], ah, bh[nt]);
#pragma unroll
                for (int nt = 0; nt < 8; nt++) mma16816(acc[mt][nt], ah, bl[nt]);
#pragma unroll
                for (int nt = 0; nt < 8; nt++) mma16816(acc[mt][nt], al, bh[nt]);
            }
        }
        __syncthreads();   // buffer-reuse barrier
    }

    // ---- Epilogue ----
    const int cpair = 2 * (lane & 3);
    if (MODE == 1) {
#pragma unroll
        for (int mt = 0; mt < 4; mt++)
#pragma unroll
            for (int half = 0; half < 2; half++) {
                const int m = m0 + wm + mt * 16 + (lane >> 2) + half * 8;
                float* dst = outp + (size_t)m * DM_ + j0 + wn + cpair;
#pragma unroll
                for (int nt = 0; nt < 8; nt++)
                    *(float2*)(dst + nt * 8) =
                        make_float2(acc[mt][nt][2 * half], acc[mt][nt][2 * half + 1]);
            }
    } else {
        const int jb = j0 + wn;
        const bool isV = (jb >= 2560);
        const bool isQ = (jb < 2048);
        const int head = isQ ? (jb >> 6) : (jb < 2560 ? ((jb - 2048) >> 6) : ((jb - 2560) >> 6));
        double invf[8];
        if (!isV) {
#pragma unroll
            for (int nt = 0; nt < 8; nt++) {
                const int pi = nt * 4 + (lane & 3);
                invf[nt] = exp2(-(2.0 * pi) * (LOG2_THETA / 64.0));
            }
        }
#pragma unroll
        for (int mt = 0; mt < 4; mt++)
#pragma unroll
            for (int half = 0; half < 2; half++) {
                const int m = m0 + wm + mt * 16 + (lane >> 2) + half * 8;
                const int bb = m >> 11;
                const int t  = m & (T_ - 1);
                if (isV) {
                    const size_t doff =
                        (((size_t)bb * HKV_ + head) * T_ + t) * HD_ + cpair;
#pragma unroll
                    for (int nt = 0; nt < 8; nt++) {
                        uint32_t lo;
                        uint32_t hi = pack_hl(acc[mt][nt][2 * half],
                                              acc[mt][nt][2 * half + 1], lo);
                        *(uint32_t*)(g_Vhi + doff + nt * 8) = hi;
                        *(uint32_t*)(g_Vlo + doff + nt * 8) = lo;
                    }
                } else {
                    const int p = pos[t];
                    const float qs = isQ ? 0.125f : 1.0f;
                    const size_t doff = isQ
                        ? (((size_t)bb * HQ_  + head) * T_ + t) * HD_ + cpair
                        : (((size_t)bb * HKV_ + head) * T_ + t) * HD_ + cpair;
                    __nv_bfloat16* dsth = isQ ? g_Qhi : g_Khi;
                    __nv_bfloat16* dstl = isQ ? g_Qlo : g_Klo;
#pragma unroll
                    for (int nt = 0; nt < 8; nt++) {
                        double sn, cs;
                        sincos((double)p * invf[nt], &sn, &cs);
                        const float fc = (float)cs, fs = (float)sn;
                        const float fe = acc[mt][nt][2 * half];
                        const float fo = acc[mt][nt][2 * half + 1];
                        uint32_t lo;
                        uint32_t hi = pack_hl((fe * fc - fo * fs) * qs,
                                              (fe * fs + fo * fc) * qs, lo);
                        *(uint32_t*)(dsth + doff + nt * 8) = hi;
                        *(uint32_t*)(dstl + doff + nt * 8) = lo;
                    }
                }
            }
    }
}

// ============================================================================
// Causal GQA flash attention on tensor cores (mma.sync, split-fp32).
// R8 structure + Q fragments hoisted to registers (loop-invariant):
// removes 16 of 80 ldsm.x4 per kt iteration. 72 KB dyn smem -> 2 CTAs/SM.
// ============================================================================
#define APAD 72
#define ATTN_SMEM_BYTES ((128 * APAD * 2 + 64 * APAD * 4) * 2)

__global__ __launch_bounds__(128, 2)
void attn_mma_kernel()
{
    extern __shared__ __nv_bfloat16 smb[];
    __nv_bfloat16* Qh = smb;                   // [128][APAD]
    __nv_bfloat16* Ql = Qh + 128 * APAD;
    __nv_bfloat16* Kh = Ql + 128 * APAD;       // [64][APAD]
    __nv_bfloat16* Kl = Kh + 64 * APAD;
    __nv_bfloat16* Vh = Kl + 64 * APAD;
    __nv_bfloat16* Vl = Vh + 64 * APAD;

    const int qt = (int)gridDim.x - 1 - (int)blockIdx.x;
    const int hq = blockIdx.y;
    const int bb = blockIdx.z;
    const int hk = hq >> 2;

    const int tid = threadIdx.x;
    const int wid = tid >> 5, lane = tid & 31;
    const int wm = wid * 32;
    const int gID = lane >> 2, tig = lane & 3;

    const uint32_t QhB = smem_u32(Qh), QlB = smem_u32(Ql);
    const uint32_t KhB = smem_u32(Kh), KlB = smem_u32(Kl);
    const uint32_t VhB = smem_u32(Vh), VlB = smem_u32(Vl);

    // Load Q tile (hi/lo) into smem
    {
        const size_t qoff = (((size_t)bb * HQ_ + hq) * T_ + (size_t)qt * 128 + tid) * HD_;
#pragma unroll
        for (int v = 0; v < 8; v++) {
            *(uint4*)&Qh[tid * APAD + v * 8] = *(const uint4*)(g_Qhi + qoff + v * 8);
            *(uint4*)&Ql[tid * APAD + v * 8] = *(const uint4*)(g_Qlo + qoff + v * 8);
        }
    }
    __syncthreads();

    // Hoist Q fragments (loop-invariant): [ks][mt] hi/lo
    uint32_t qfh[4][2][4], qfl[4][2][4];
#pragma unroll
    for (int ks = 0; ks < 4; ks++) {
        const int arow = wm + (lane & 15);
        const int acol = ks * 16 + (lane >> 4) * 8;
#pragma unroll
        for (int mt = 0; mt < 2; mt++) {
            const uint32_t off = (uint32_t)((arow + mt * 16) * APAD + acol) * 2u;
            ldsm_x4(qfh[ks][mt][0], qfh[ks][mt][1], qfh[ks][mt][2], qfh[ks][mt][3],
                    QhB + off);
            ldsm_x4(qfl[ks][mt][0], qfl[ks][mt][1], qfl[ks][mt][2], qfl[ks][mt][3],
                    QlB + off);
        }
    }

    float O[2][8][4];
#pragma unroll
    for (int mt = 0; mt < 2; mt++)
#pragma unroll
        for (int nt = 0; nt < 8; nt++)
#pragma unroll
            for (int q = 0; q < 4; q++) O[mt][nt][q] = 0.f;
    float m_st[2][2], l_st[2][2];
#pragma unroll
    for (int mt = 0; mt < 2; mt++)
#pragma unroll
        for (int h2 = 0; h2 < 2; h2++) { m_st[mt][h2] = -FLT_MAX; l_st[mt][h2] = 0.f; }

    const size_t kvbase = ((size_t)bb * HKV_ + hk) * T_ * HD_;
    const int lrow = tid >> 1;
    const int lhalf = (tid & 1) * 32;
    const int ktmax = 2 * qt + 1;

    for (int kt = 0; kt <= ktmax; kt++) {
        __syncthreads();   // WAR vs previous iteration's ldsm reads
        {
            const size_t goff = kvbase + ((size_t)kt * 64 + lrow) * HD_ + lhalf;
            const int soff = lrow * APAD + lhalf;
#pragma unroll
            for (int v = 0; v < 4; v++) {
                *(uint4*)&Kh[soff + v * 8] = *(const uint4*)(g_Khi + goff + v * 8);
                *(uint4*)&Kl[soff + v * 8] = *(const uint4*)(g_Klo + goff + v * 8);
                *(uint4*)&Vh[soff + v * 8] = *(const uint4*)(g_Vhi + goff + v * 8);
                *(uint4*)&Vl[soff + v * 8] = *(const uint4*)(g_Vlo + goff + v * 8);
            }
        }
        __syncthreads();

        // ---- S = Q K^T (3 passes) ----
        float S[2][8][4];
#pragma unroll
        for (int mt = 0; mt < 2; mt++)
#pragma unroll
            for (int nt = 0; nt < 8; nt++)
#pragma unroll
                for (int q = 0; q < 4; q++) S[mt][nt][q] = 0.f;

#pragma unroll
        for (int ks = 0; ks < 4; ks++) {
            uint32_t bh[8][2], bl[8][2];
            const int brow = ((lane >> 4) & 1) * 8 + (lane & 7);
            const int bcol = ks * 16 + ((lane >> 3) & 1) * 8;
#pragma unroll
            for (int p = 0; p < 4; p++) {
                const uint32_t off = (uint32_t)((brow + p * 16) * APAD + bcol) * 2u;
                ldsm_x4(bh[2*p][0], bh[2*p][1], bh[2*p+1][0], bh[2*p+1][1], KhB + off);
                ldsm_x4(bl[2*p][0], bl[2*p][1], bl[2*p+1][0], bl[2*p+1][1], KlB + off);
            }
#pragma unroll
            for (int mt = 0; mt < 2; mt++) {
#pragma unroll
                for (int nt = 0; nt < 8; nt++) mma16816(S[mt][nt], qfh[ks][mt], bh[nt]);
#pragma unroll
                for (int nt = 0; nt < 8; nt++) mma16816(S[mt][nt], qfh[ks][mt], bl[nt]);
#pragma unroll
                for (int nt = 0; nt < 8; nt++) mma16816(S[mt][nt], qfl[ks][mt], bh[nt]);
            }
        }

        // ---- Causal mask (diagonal tiles only) ----
        if (kt >= 2 * qt) {
            const int rg = qt * 128 + wm + gID;
            const int cg = kt * 64 + 2 * tig;
#pragma unroll
            for (int mt = 0; mt < 2; mt++)
#pragma unroll
                for (int nt = 0; nt < 8; nt++)
#pragma unroll
                    for (int h2 = 0; h2 < 2; h2++)
#pragma unroll
                        for (int e = 0; e < 2; e++)
                            if (cg + nt * 8 + e > rg + mt * 16 + h2 * 8)
                                S[mt][nt][2 * h2 + e] = -FLT_MAX;
        }

        // ---- Online softmax (quad rows; shfl_xor 1,2) ----
#pragma unroll
        for (int mt = 0; mt < 2; mt++)
#pragma unroll
            for (int h2 = 0; h2 < 2; h2++) {
                float mx = -FLT_MAX;
#pragma unroll
                for (int nt = 0; nt < 8; nt++)
                    mx = fmaxf(mx, fmaxf(S[mt][nt][2 * h2], S[mt][nt][2 * h2 + 1]));
                mx = fmaxf(mx, __shfl_xor_sync(0xffffffffu, mx, 1));
                mx = fmaxf(mx, __shfl_xor_sync(0xffffffffu, mx, 2));
                const float nm = fmaxf(m_st[mt][h2], mx);
                float sum = 0.f;
#pragma unroll
                for (int nt = 0; nt < 8; nt++) {
                    S[mt][nt][2 * h2]     = __expf(S[mt][nt][2 * h2]     - nm);
                    S[mt][nt][2 * h2 + 1] = __expf(S[mt][nt][2 * h2 + 1] - nm);
                    sum += S[mt][nt][2 * h2] + S[mt][nt][2 * h2 + 1];
                }
                sum += __shfl_xor_sync(0xffffffffu, sum, 1);
                sum += __shfl_xor_sync(0xffffffffu, sum, 2);
                const float corr = __expf(m_st[mt][h2] - nm);
                m_st[mt][h2] = nm;
                l_st[mt][h2] = l_st[mt][h2] * corr + sum;
#pragma unroll
                for (int nt = 0; nt < 8; nt++) {
                    O[mt][nt][2 * h2]     *= corr;
                    O[mt][nt][2 * h2 + 1] *= corr;
                }
            }

        // ---- O += P V (3 passes; P packed register-locally) ----
#pragma unroll
        for (int ks = 0; ks < 4; ks++) {
            uint32_t vh[8][2], vl[8][2];
            const int vrow = ks * 16 + (lane & 15);
#pragma unroll
            for (int p = 0; p < 4; p++) {
                const uint32_t off =
                    (uint32_t)(vrow * APAD + p * 16 + (lane >> 4) * 8) * 2u;
                ldsm_x4_t(vh[2*p][0], vh[2*p][1], vh[2*p+1][0], vh[2*p+1][1], VhB + off);
                ldsm_x4_t(vl[2*p][0], vl[2*p][1], vl[2*p+1][0], vl[2*p+1][1], VlB + off);
            }
#pragma unroll
            for (int mt = 0; mt < 2; mt++) {
                uint32_t ah[4], al[4];
                ah[0] = pack_hl(S[mt][2*ks][0],   S[mt][2*ks][1],   al[0]);
                ah[1] = pack_hl(S[mt][2*ks][2],   S[mt][2*ks][3],   al[1]);
                ah[2] = pack_hl(S[mt][2*ks+1][0], S[mt][2*ks+1][1], al[2]);
                ah[3] = pack_hl(S[mt][2*ks+1][2], S[mt][2*ks+1][3], al[3]);
#pragma unroll
                for (int nt = 0; nt < 8; nt++) mma16816(O[mt][nt], ah, vh[nt]);
#pragma unroll
                for (int nt = 0; nt < 8; nt++) mma16816(O[mt][nt], ah, vl[nt]);
#pragma unroll
                for (int nt = 0; nt < 8; nt++) mma16816(O[mt][nt], al, vh[nt]);
            }
        }
    }

    // ---- Finalize: /l, split hi/lo, store for out-projection ----
#pragma unroll
    for (int mt = 0; mt < 2; mt++)
#pragma unroll
        for (int h2 = 0; h2 < 2; h2++) {
            const float inv = 1.0f / l_st[mt][h2];
            const int rg = qt * 128 + wm + mt * 16 + gID + h2 * 8;
            const size_t off = ((size_t)bb * T_ + rg) * DM_ + hq * HD_ + 2 * tig;
#pragma unroll
            for (int nt = 0; nt < 8; nt++) {
                uint32_t lo;
                uint32_t hi = pack_hl(O[mt][nt][2 * h2] * inv,
                                      O[mt][nt][2 * h2 + 1] * inv, lo);
                *(uint32_t*)(g_Ohi + off + nt * 8) = hi;
                *(uint32_t*)(g_Olo + off + nt * 8) = lo;
            }
        }
}

// ============================================================================
extern "C" void kernel_launch(void* const* d_in, const int* in_sizes, int n_in,
                              void* d_out, int out_size)
{
    const float* x   = (const float*)d_in[0];
    const int*   pos = (const int*)  d_in[1];
    const float* WQ  = (const float*)d_in[2];
    const float* WK  = (const float*)d_in[3];
    const float* WV  = (const float*)d_in[4];
    const float* WO  = (const float*)d_in[5];
    float* out = (float*)d_out;

    cudaFuncSetAttribute(gemm_mma_kernel<0>, cudaFuncAttributeMaxDynamicSharedMemorySize,
                         GEMM_SMEM_BYTES);
    cudaFuncSetAttribute(gemm_mma_kernel<1>, cudaFuncAttributeMaxDynamicSharedMemorySize,
                         GEMM_SMEM_BYTES);
    cudaFuncSetAttribute(attn_mma_kernel, cudaFuncAttributeMaxDynamicSharedMemorySize,
                         ATTN_SMEM_BYTES);

    // 0) hi/lo bf16 conversion of x and all weights
    cvt_kernel<<<CVT_TOTAL_F4 / 256, 256>>>(x, WQ, WK, WV, WO);

    // 1) QKV projection + RoPE (tensor cores) -> bf16 hi/lo Q/K/V
    gemm_mma_kernel<0><<<dim3(24, (B_ * T_) / 256), 256, GEMM_SMEM_BYTES>>>(pos, nullptr);

    // 2) Flash attention (tensor cores, split-fp32) -> bf16 hi/lo O
    attn_mma_kernel<<<dim3(T_ / 128, HQ_, B_), 128, ATTN_SMEM_BYTES>>>();

    // 3) Output projection (tensor cores) -> fp32 out
    gemm_mma_kernel<1><<<dim3(16, (B_ * T_) / 256), 256, GEMM_SMEM_BYTES>>>(pos, out);
}

// round 14
// speedup vs baseline: 1.2401x; 1.2401x over previous
#include <cuda_runtime.h>
#include <cuda_bf16.h>
#include <math.h>
#include <float.h>
#include <stdint.h>

// Problem constants
#define B_    2
#define T_    2048
#define DM_   2048
#define HQ_   32
#define HKV_  8
#define HD_   64
#define LOG2_THETA 13.287712379549449

// bf16 hi/lo split buffers (no allocs -> __device__ globals)
__device__ __nv_bfloat16 g_xhi[(size_t)4096 * 2048];
__device__ __nv_bfloat16 g_xlo[(size_t)4096 * 2048];
__device__ __nv_bfloat16 g_Whi[(size_t)3072 * 2048];   // WQ|WK|WV rows
__device__ __nv_bfloat16 g_Wlo[(size_t)3072 * 2048];
__device__ __nv_bfloat16 g_WOhi[(size_t)2048 * 2048];
__device__ __nv_bfloat16 g_WOlo[(size_t)2048 * 2048];
__device__ __nv_bfloat16 g_Ohi[(size_t)4096 * 2048];   // attention out
__device__ __nv_bfloat16 g_Olo[(size_t)4096 * 2048];
__device__ __nv_bfloat16 g_Qhi[(size_t)B_ * HQ_  * T_ * HD_];  // rope'd, pre-scaled
__device__ __nv_bfloat16 g_Qlo[(size_t)B_ * HQ_  * T_ * HD_];
__device__ __nv_bfloat16 g_Khi[(size_t)B_ * HKV_ * T_ * HD_];  // rope'd
__device__ __nv_bfloat16 g_Klo[(size_t)B_ * HKV_ * T_ * HD_];
__device__ __nv_bfloat16 g_Vhi[(size_t)B_ * HKV_ * T_ * HD_];
__device__ __nv_bfloat16 g_Vlo[(size_t)B_ * HKV_ * T_ * HD_];

// ============================================================================
// PTX helpers (legacy tensor path: plain PTX, valid on compute_103)
// ============================================================================
__device__ __forceinline__ uint32_t smem_u32(const void* p) {
    uint32_t a;
    asm("{ .reg .u64 t; cvta.to.shared.u64 t, %1; cvt.u32.u64 %0, t; }"
        : "=r"(a) : "l"(p));
    return a;
}
__device__ __forceinline__ void ldsm_x4(uint32_t& r0, uint32_t& r1,
                                        uint32_t& r2, uint32_t& r3, uint32_t a) {
    asm volatile("ldmatrix.sync.aligned.m8n8.x4.shared.b16 {%0,%1,%2,%3}, [%4];"
                 : "=r"(r0), "=r"(r1), "=r"(r2), "=r"(r3) : "r"(a));
}
__device__ __forceinline__ void ldsm_x4_t(uint32_t& r0, uint32_t& r1,
                                          uint32_t& r2, uint32_t& r3, uint32_t a) {
    asm volatile("ldmatrix.sync.aligned.m8n8.x4.trans.shared.b16 {%0,%1,%2,%3}, [%4];"
                 : "=r"(r0), "=r"(r1), "=r"(r2), "=r"(r3) : "r"(a));
}
__device__ __forceinline__ void mma16816(float* d, const uint32_t* a, const uint32_t* b) {
    asm volatile(
        "mma.sync.aligned.m16n8k16.row.col.f32.bf16.bf16.f32 "
        "{%0,%1,%2,%3}, {%4,%5,%6,%7}, {%8,%9}, {%0,%1,%2,%3};"
        : "+f"(d[0]), "+f"(d[1]), "+f"(d[2]), "+f"(d[3])
        : "r"(a[0]), "r"(a[1]), "r"(a[2]), "r"(a[3]), "r"(b[0]), "r"(b[1]));
}
__device__ __forceinline__ void split1(float v, __nv_bfloat16& h, __nv_bfloat16& l) {
    h = __float2bfloat16_rn(v);
    l = __float2bfloat16_rn(v - __bfloat162float(h));
}
__device__ __forceinline__ uint32_t pack_hl(float a, float b, uint32_t& lo) {
    __nv_bfloat16 ha, hb, la, lb;
    split1(a, ha, la);
    split1(b, hb, lb);
    lo = (uint32_t)__bfloat16_as_ushort(la) | ((uint32_t)__bfloat16_as_ushort(lb) << 16);
    return (uint32_t)__bfloat16_as_ushort(ha) | ((uint32_t)__bfloat16_as_ushort(hb) << 16);
}

// ============================================================================
// Kernel 0: fp32 -> (hi, lo) bf16 conversion for x, WQ|WK|WV, WO.
// ============================================================================
#define NE_X   8388608ull
#define NE_WQ  4194304ull
#define NE_WKV 1048576ull
#define CVT_TOTAL_F4 4718592

__global__ __launch_bounds__(256)
void cvt_kernel(const float* __restrict__ x,  const float* __restrict__ WQ,
                const float* __restrict__ WK, const float* __restrict__ WV,
                const float* __restrict__ WO)
{
    const size_t e = ((size_t)blockIdx.x * 256 + threadIdx.x) * 4;
    const float* src; __nv_bfloat16 *dh, *dl; size_t off;
    if (e < NE_X)                          { src = x;  dh = g_xhi;            dl = g_xlo;            off = e; }
    else if (e < NE_X + NE_WQ)             { src = WQ; dh = g_Whi;            dl = g_Wlo;            off = e - NE_X; }
    else if (e < NE_X + NE_WQ + NE_WKV)    { src = WK; dh = g_Whi + 4194304;  dl = g_Wlo + 4194304;  off = e - NE_X - NE_WQ; }
    else if (e < NE_X + NE_WQ + 2*NE_WKV)  { src = WV; dh = g_Whi + 5242880;  dl = g_Wlo + 5242880;  off = e - NE_X - NE_WQ - NE_WKV; }
    else                                   { src = WO; dh = g_WOhi;           dl = g_WOlo;           off = e - NE_X - NE_WQ - 2*NE_WKV; }
    float4 v = *(const float4*)(src + off);
    uint2 uh, ul;
    uh.x = pack_hl(v.x, v.y, ul.x);
    uh.y = pack_hl(v.z, v.w, ul.y);
    *(uint2*)(dh + off) = uh;
    *(uint2*)(dl + off) = ul;
}

// ============================================================================
// mma.sync split-fp32 GEMM (R10-proven, FROZEN): D[128x128] = A * B^T, BK=32.
// 256 thr = 8 warps (4m x 2n), warp tile 32x64. Double-buffered smem, ONE
// barrier per chunk. 128-reg cap -> 2 CTA/SM.
// MODE 0: QKV proj -> RoPE -> hi/lo bf16 Q/K/V (Q pre-scaled by 0.125).
// MODE 1: out proj -> fp32 to outp.
// ============================================================================
#define SPAD 40
#define GREG_ELEMS 5120                      // 128*SPAD bf16 per region
#define GREG_B 10240u                        // bytes per region
#define GEMM_SMEM_BYTES (8 * GREG_B)         // 2 bufs x {Ahi,Alo,Bhi,Blo}

template <int MODE>
__global__ __launch_bounds__(256, 2)
void gemm_mma_kernel(const int* __restrict__ pos, float* __restrict__ outp)
{
    extern __shared__ __align__(16) __nv_bfloat16 smg[];
    const uint32_t smBase = smem_u32(smg);

    const int j0 = blockIdx.x * 128;
    const int m0 = blockIdx.y * 128;
    const int tid = threadIdx.x;
    const int wid = tid >> 5, lane = tid & 31;

    const __nv_bfloat16* Ahi = (MODE == 0) ? g_xhi : g_Ohi;
    const __nv_bfloat16* Alo = (MODE == 0) ? g_xlo : g_Olo;
    const __nv_bfloat16* Bhi = ((MODE == 0) ? g_Whi : g_WOhi) + (size_t)j0 * DM_;
    const __nv_bfloat16* Blo = ((MODE == 0) ? g_Wlo : g_WOlo) + (size_t)j0 * DM_;

    const int lrow = tid >> 1;
    const int lcol = (tid & 1) * 16;
    const size_t aoff = (size_t)(m0 + lrow) * DM_ + lcol;
    const size_t boff = (size_t)lrow * DM_ + lcol;
    const int sidx = lrow * SPAD + lcol;

    const int wm = (wid & 3) * 32;
    const int wn = (wid >> 2) * 64;

    float acc[2][8][4];
#pragma unroll
    for (int mt = 0; mt < 2; mt++)
#pragma unroll
        for (int nt = 0; nt < 8; nt++)
#pragma unroll
            for (int q = 0; q < 4; q++) acc[mt][nt][q] = 0.f;

    auto load_chunk = [&](int kc, int buf) {
        const size_t nk = (size_t)kc * 32;
        __nv_bfloat16* p = smg + (size_t)buf * (4 * GREG_ELEMS);
        *(uint4*)&p[sidx]                      = *(const uint4*)(Ahi + aoff + nk);
        *(uint4*)&p[sidx + 8]                  = *(const uint4*)(Ahi + aoff + nk + 8);
        *(uint4*)&p[GREG_ELEMS + sidx]         = *(const uint4*)(Alo + aoff + nk);
        *(uint4*)&p[GREG_ELEMS + sidx + 8]     = *(const uint4*)(Alo + aoff + nk + 8);
        *(uint4*)&p[2 * GREG_ELEMS + sidx]     = *(const uint4*)(Bhi + boff + nk);
        *(uint4*)&p[2 * GREG_ELEMS + sidx + 8] = *(const uint4*)(Bhi + boff + nk + 8);
        *(uint4*)&p[3 * GREG_ELEMS + sidx]     = *(const uint4*)(Blo + boff + nk);
        *(uint4*)&p[3 * GREG_ELEMS + sidx + 8] = *(const uint4*)(Blo + boff + nk + 8);
    };

    load_chunk(0, 0);
    __syncthreads();

    for (int kc = 0; kc < DM_ / 32; kc++) {
        if (kc + 1 < DM_ / 32) load_chunk(kc + 1, (kc + 1) & 1);

        const uint32_t aB = smBase + (uint32_t)(kc & 1) * (4 * GREG_B);
        const uint32_t bB = aB + 2 * GREG_B;

#pragma unroll
        for (int ks = 0; ks < 2; ks++) {
            uint32_t bh[8][2], bl[8][2];
            const int brow = wn + ((lane >> 4) & 1) * 8 + (lane & 7);
            const int bcol = ks * 16 + ((lane >> 3) & 1) * 8;
#pragma unroll
            for (int p = 0; p < 4; p++) {
                const uint32_t off = (uint32_t)((brow + p * 16) * SPAD + bcol) * 2u;
                ldsm_x4(bh[2*p][0], bh[2*p][1], bh[2*p+1][0], bh[2*p+1][1], bB + off);
                ldsm_x4(bl[2*p][0], bl[2*p][1], bl[2*p+1][0], bl[2*p+1][1],
                        bB + GREG_B + off);
            }
            const int arow = wm + (lane & 15);
            const int acol = ks * 16 + (lane >> 4) * 8;
#pragma unroll
            for (int mt = 0; mt < 2; mt++) {
                uint32_t ah[4], al[4];
                const uint32_t off = (uint32_t)((arow + mt * 16) * SPAD + acol) * 2u;
                ldsm_x4(ah[0], ah[1], ah[2], ah[3], aB + off);
                ldsm_x4(al[0], al[1], al[2], al[3], aB + GREG_B + off);
#pragma unroll
                for (int nt = 0; nt < 8; nt++) mma16816(acc[mt][nt], ah, bh[nt]);
#pragma unroll
                for (int nt = 0; nt < 8; nt++) mma16816(acc[mt][nt], ah, bl[nt]);
#pragma unroll
                for (int nt = 0; nt < 8; nt++) mma16816(acc[mt][nt], al, bh[nt]);
            }
        }
        __syncthreads();   // buffer-reuse barrier
    }

    // ---- Epilogue ----
    const int cpair = 2 * (lane & 3);
    if (MODE == 1) {
#pragma unroll
        for (int mt = 0; mt < 2; mt++)
#pragma unroll
            for (int half = 0; half < 2; half++) {
                const int m = m0 + wm + mt * 16 + (lane >> 2) + half * 8;
                float* dst = outp + (size_t)m * DM_ + j0 + wn + cpair;
#pragma unroll
                for (int nt = 0; nt < 8; nt++)
                    *(float2*)(dst + nt * 8) =
                        make_float2(acc[mt][nt][2 * half], acc[mt][nt][2 * half + 1]);
            }
    } else {
        const int jb = j0 + wn;
        const bool isV = (jb >= 2560);
        const bool isQ = (jb < 2048);
        const int head = isQ ? (jb >> 6) : (jb < 2560 ? ((jb - 2048) >> 6) : ((jb - 2560) >> 6));
        double invf[8];
        if (!isV) {
#pragma unroll
            for (int nt = 0; nt < 8; nt++) {
                const int pi = nt * 4 + (lane & 3);
                invf[nt] = exp2(-(2.0 * pi) * (LOG2_THETA / 64.0));
            }
        }
#pragma unroll
        for (int mt = 0; mt < 2; mt++)
#pragma unroll
            for (int half = 0; half < 2; half++) {
                const int m = m0 + wm + mt * 16 + (lane >> 2) + half * 8;
                const int bb = m >> 11;
                const int t  = m & (T_ - 1);
                if (isV) {
                    const size_t doff =
                        (((size_t)bb * HKV_ + head) * T_ + t) * HD_ + cpair;
#pragma unroll
                    for (int nt = 0; nt < 8; nt++) {
                        uint32_t lo;
                        uint32_t hi = pack_hl(acc[mt][nt][2 * half],
                                              acc[mt][nt][2 * half + 1], lo);
                        *(uint32_t*)(g_Vhi + doff + nt * 8) = hi;
                        *(uint32_t*)(g_Vlo + doff + nt * 8) = lo;
                    }
                } else {
                    const int p = pos[t];
                    const float qs = isQ ? 0.125f : 1.0f;
                    const size_t doff = isQ
                        ? (((size_t)bb * HQ_  + head) * T_ + t) * HD_ + cpair
                        : (((size_t)bb * HKV_ + head) * T_ + t) * HD_ + cpair;
                    __nv_bfloat16* dsth = isQ ? g_Qhi : g_Khi;
                    __nv_bfloat16* dstl = isQ ? g_Qlo : g_Klo;
#pragma unroll
                    for (int nt = 0; nt < 8; nt++) {
                        double sn, cs;
                        sincos((double)p * invf[nt], &sn, &cs);
                        const float fc = (float)cs, fs = (float)sn;
                        const float fe = acc[mt][nt][2 * half];
                        const float fo = acc[mt][nt][2 * half + 1];
                        uint32_t lo;
                        uint32_t hi = pack_hl((fe * fc - fo * fs) * qs,
                                              (fe * fs + fo * fc) * qs, lo);
                        *(uint32_t*)(dsth + doff + nt * 8) = hi;
                        *(uint32_t*)(dstl + doff + nt * 8) = lo;
                    }
                }
            }
    }
}

// ============================================================================
// Causal GQA flash attention on tensor cores (mma.sync, split-fp32).
// R8 body + (a) double-buffered K/V with ONE barrier per iteration
// (LDG->STS into the other buffer, R10-GEMM-proven scheme), (b) Q-hi
// fragments hoisted to registers (+32 regs, -8 ldsm/iter).
// 128 thr = 4 warps; BM=128, BN=64. 108 KB dyn smem -> 2 CTAs/SM.
// ============================================================================
#define APAD 72
#define AQ_ELEMS (128 * APAD)                 // 9216
#define AKV_ELEMS (64 * APAD)                 // 4608
#define KVBUF_ELEMS (4 * AKV_ELEMS)           // Kh,Kl,Vh,Vl
#define ATTN_SMEM_BYTES ((2 * AQ_ELEMS + 2 * KVBUF_ELEMS) * 2)   // 110592 B

__global__ __launch_bounds__(128, 2)
void attn_mma_kernel()
{
    extern __shared__ __align__(16) __nv_bfloat16 smb[];
    const uint32_t smBase = smem_u32(smb);
    const uint32_t QhB = smBase;
    const uint32_t QlB = smBase + AQ_ELEMS * 2;
    const uint32_t KV0 = smBase + 4 * AQ_ELEMS;      // bytes: 2*AQ_ELEMS*2

    const int qt = (int)gridDim.x - 1 - (int)blockIdx.x;
    const int hq = blockIdx.y;
    const int bb = blockIdx.z;
    const int hk = hq >> 2;

    const int tid = threadIdx.x;
    const int wid = tid >> 5, lane = tid & 31;
    const int wm = wid * 32;
    const int gID = lane >> 2, tig = lane & 3;

    // Load Q tile (hi/lo) into smem
    {
        const size_t qoff = (((size_t)bb * HQ_ + hq) * T_ + (size_t)qt * 128 + tid) * HD_;
        __nv_bfloat16* Qh = smb;
        __nv_bfloat16* Ql = smb + AQ_ELEMS;
#pragma unroll
        for (int v = 0; v < 8; v++) {
            *(uint4*)&Qh[tid * APAD + v * 8] = *(const uint4*)(g_Qhi + qoff + v * 8);
            *(uint4*)&Ql[tid * APAD + v * 8] = *(const uint4*)(g_Qlo + qoff + v * 8);
        }
    }
    __syncthreads();

    // Hoist Q-hi fragments (loop-invariant): [ks][mt]
    uint32_t qfh[4][2][4];
#pragma unroll
    for (int ks = 0; ks < 4; ks++) {
        const int arow = wm + (lane & 15);
        const int acol = ks * 16 + (lane >> 4) * 8;
#pragma unroll
        for (int mt = 0; mt < 2; mt++) {
            const uint32_t off = (uint32_t)((arow + mt * 16) * APAD + acol) * 2u;
            ldsm_x4(qfh[ks][mt][0], qfh[ks][mt][1], qfh[ks][mt][2], qfh[ks][mt][3],
                    QhB + off);
        }
    }

    float O[2][8][4];
#pragma unroll
    for (int mt = 0; mt < 2; mt++)
#pragma unroll
        for (int nt = 0; nt < 8; nt++)
#pragma unroll
            for (int q = 0; q < 4; q++) O[mt][nt][q] = 0.f;
    float m_st[2][2], l_st[2][2];
#pragma unroll
    for (int mt = 0; mt < 2; mt++)
#pragma unroll
        for (int h2 = 0; h2 < 2; h2++) { m_st[mt][h2] = -FLT_MAX; l_st[mt][h2] = 0.f; }

    const size_t kvbase = ((size_t)bb * HKV_ + hk) * T_ * HD_;
    const int lrow = tid >> 1;
    const int lhalf = (tid & 1) * 32;
    const int ktmax = 2 * qt + 1;

    auto load_kv = [&](int kt, int buf) {
        const size_t goff = kvbase + ((size_t)kt * 64 + lrow) * HD_ + lhalf;
        __nv_bfloat16* p = smb + 2 * AQ_ELEMS + (size_t)buf * KVBUF_ELEMS;
        const int soff = lrow * APAD + lhalf;
#pragma unroll
        for (int v = 0; v < 4; v++) {
            *(uint4*)&p[soff + v * 8]                 = *(const uint4*)(g_Khi + goff + v * 8);
            *(uint4*)&p[AKV_ELEMS + soff + v * 8]     = *(const uint4*)(g_Klo + goff + v * 8);
            *(uint4*)&p[2 * AKV_ELEMS + soff + v * 8] = *(const uint4*)(g_Vhi + goff + v * 8);
            *(uint4*)&p[3 * AKV_ELEMS + soff + v * 8] = *(const uint4*)(g_Vlo + goff + v * 8);
        }
    };

    load_kv(0, 0);
    __syncthreads();

    for (int kt = 0; kt <= ktmax; kt++) {
        if (kt < ktmax) load_kv(kt + 1, (kt + 1) & 1);   // prefetch other buffer

        const uint32_t kb  = KV0 + (uint32_t)(kt & 1) * (KVBUF_ELEMS * 2);
        const uint32_t KhA = kb;
        const uint32_t KlA = kb + AKV_ELEMS * 2;
        const uint32_t VhA = kb + 2 * AKV_ELEMS * 2;
        const uint32_t VlA = kb + 3 * AKV_ELEMS * 2;

        // ---- S = Q K^T (3 passes; Q-hi from registers) ----
        float S[2][8][4];
#pragma unroll
        for (int mt = 0; mt < 2; mt++)
#pragma unroll
            for (int nt = 0; nt < 8; nt++)
#pragma unroll
                for (int q = 0; q < 4; q++) S[mt][nt][q] = 0.f;

#pragma unroll
        for (int ks = 0; ks < 4; ks++) {
            uint32_t bh[8][2], bl[8][2];
            const int brow = ((lane >> 4) & 1) * 8 + (lane & 7);
            const int bcol = ks * 16 + ((lane >> 3) & 1) * 8;
#pragma unroll
            for (int p = 0; p < 4; p++) {
                const uint32_t off = (uint32_t)((brow + p * 16) * APAD + bcol) * 2u;
                ldsm_x4(bh[2*p][0], bh[2*p][1], bh[2*p+1][0], bh[2*p+1][1], KhA + off);
                ldsm_x4(bl[2*p][0], bl[2*p][1], bl[2*p+1][0], bl[2*p+1][1], KlA + off);
            }
            const int arow = wm + (lane & 15);
            const int acol = ks * 16 + (lane >> 4) * 8;
#pragma unroll
            for (int mt = 0; mt < 2; mt++) {
                uint32_t al[4];
                const uint32_t off = (uint32_t)((arow + mt * 16) * APAD + acol) * 2u;
                ldsm_x4(al[0], al[1], al[2], al[3], QlB + off);
#pragma unroll
                for (int nt = 0; nt < 8; nt++) mma16816(S[mt][nt], qfh[ks][mt], bh[nt]);
#pragma unroll
                for (int nt = 0; nt < 8; nt++) mma16816(S[mt][nt], qfh[ks][mt], bl[nt]);
#pragma unroll
                for (int nt = 0; nt < 8; nt++) mma16816(S[mt][nt], al, bh[nt]);
            }
        }

        // ---- Causal mask (diagonal tiles only) ----
        if (kt >= 2 * qt) {
            const int rg = qt * 128 + wm + gID;
            const int cg = kt * 64 + 2 * tig;
#pragma unroll
            for (int mt = 0; mt < 2; mt++)
#pragma unroll
                for (int nt = 0; nt < 8; nt++)
#pragma unroll
                    for (int h2 = 0; h2 < 2; h2++)
#pragma unroll
                        for (int e = 0; e < 2; e++)
                            if (cg + nt * 8 + e > rg + mt * 16 + h2 * 8)
                                S[mt][nt][2 * h2 + e] = -FLT_MAX;
        }

        // ---- Online softmax (quad rows; shfl_xor 1,2) ----
#pragma unroll
        for (int mt = 0; mt < 2; mt++)
#pragma unroll
            for (int h2 = 0; h2 < 2; h2++) {
                float mx = -FLT_MAX;
#pragma unroll
                for (int nt = 0; nt < 8; nt++)
                    mx = fmaxf(mx, fmaxf(S[mt][nt][2 * h2], S[mt][nt][2 * h2 + 1]));
                mx = fmaxf(mx, __shfl_xor_sync(0xffffffffu, mx, 1));
                mx = fmaxf(mx, __shfl_xor_sync(0xffffffffu, mx, 2));
                const float nm = fmaxf(m_st[mt][h2], mx);
                float sum = 0.f;
#pragma unroll
                for (int nt = 0; nt < 8; nt++) {
                    S[mt][nt][2 * h2]     = __expf(S[mt][nt][2 * h2]     - nm);
                    S[mt][nt][2 * h2 + 1] = __expf(S[mt][nt][2 * h2 + 1] - nm);
                    sum += S[mt][nt][2 * h2] + S[mt][nt][2 * h2 + 1];
                }
                sum += __shfl_xor_sync(0xffffffffu, sum, 1);
                sum += __shfl_xor_sync(0xffffffffu, sum, 2);
                const float corr = __expf(m_st[mt][h2] - nm);
                m_st[mt][h2] = nm;
                l_st[mt][h2] = l_st[mt][h2] * corr + sum;
#pragma unroll
                for (int nt = 0; nt < 8; nt++) {
                    O[mt][nt][2 * h2]     *= corr;
                    O[mt][nt][2 * h2 + 1] *= corr;
                }
            }

        // ---- O += P V (3 passes; P packed register-locally) ----
#pragma unroll
        for (int ks = 0; ks < 4; ks++) {
            uint32_t vh[8][2], vl[8][2];
            const int vrow = ks * 16 + (lane & 15);
#pragma unroll
            for (int p = 0; p < 4; p++) {
                const uint32_t off =
                    (uint32_t)(vrow * APAD + p * 16 + (lane >> 4) * 8) * 2u;
                ldsm_x4_t(vh[2*p][0], vh[2*p][1], vh[2*p+1][0], vh[2*p+1][1], VhA + off);
                ldsm_x4_t(vl[2*p][0], vl[2*p][1], vl[2*p+1][0], vl[2*p+1][1], VlA + off);
            }
#pragma unroll
            for (int mt = 0; mt < 2; mt++) {
                uint32_t ah[4], al[4];
                ah[0] = pack_hl(S[mt][2*ks][0],   S[mt][2*ks][1],   al[0]);
                ah[1] = pack_hl(S[mt][2*ks][2],   S[mt][2*ks][3],   al[1]);
                ah[2] = pack_hl(S[mt][2*ks+1][0], S[mt][2*ks+1][1], al[2]);
                ah[3] = pack_hl(S[mt][2*ks+1][2], S[mt][2*ks+1][3], al[3]);
#pragma unroll
                for (int nt = 0; nt < 8; nt++) mma16816(O[mt][nt], ah, vh[nt]);
#pragma unroll
                for (int nt = 0; nt < 8; nt++) mma16816(O[mt][nt], ah, vl[nt]);
#pragma unroll
                for (int nt = 0; nt < 8; nt++) mma16816(O[mt][nt], al, vh[nt]);
            }
        }
        __syncthreads();   // all reads of buffer kt&1 done -> reusable at kt+2
    }

    // ---- Finalize: /l, split hi/lo, store for out-projection ----
#pragma unroll
    for (int mt = 0; mt < 2; mt++)
#pragma unroll
        for (int h2 = 0; h2 < 2; h2++) {
            const float inv = 1.0f / l_st[mt][h2];
            const int rg = qt * 128 + wm + mt * 16 + gID + h2 * 8;
            const size_t off = ((size_t)bb * T_ + rg) * DM_ + hq * HD_ + 2 * tig;
#pragma unroll
            for (int nt = 0; nt < 8; nt++) {
                uint32_t lo;
                uint32_t hi = pack_hl(O[mt][nt][2 * h2] * inv,
                                      O[mt][nt][2 * h2 + 1] * inv, lo);
                *(uint32_t*)(g_Ohi + off + nt * 8) = hi;
                *(uint32_t*)(g_Olo + off + nt * 8) = lo;
            }
        }
}

// ============================================================================
extern "C" void kernel_launch(void* const* d_in, const int* in_sizes, int n_in,
                              void* d_out, int out_size)
{
    const float* x   = (const float*)d_in[0];
    const int*   pos = (const int*)  d_in[1];
    const float* WQ  = (const float*)d_in[2];
    const float* WK  = (const float*)d_in[3];
    const float* WV  = (const float*)d_in[4];
    const float* WO  = (const float*)d_in[5];
    float* out = (float*)d_out;

    cudaFuncSetAttribute(gemm_mma_kernel<0>, cudaFuncAttributeMaxDynamicSharedMemorySize,
                         GEMM_SMEM_BYTES);
    cudaFuncSetAttribute(gemm_mma_kernel<1>, cudaFuncAttributeMaxDynamicSharedMemorySize,
                         GEMM_SMEM_BYTES);
    cudaFuncSetAttribute(attn_mma_kernel, cudaFuncAttributeMaxDynamicSharedMemorySize,
                         ATTN_SMEM_BYTES);

    // 0) hi/lo bf16 conversion of x and all weights
    cvt_kernel<<<CVT_TOTAL_F4 / 256, 256>>>(x, WQ, WK, WV, WO);

    // 1) QKV projection + RoPE (tensor cores) -> bf16 hi/lo Q/K/V
    gemm_mma_kernel<0><<<dim3(24, (B_ * T_) / 128), 256, GEMM_SMEM_BYTES>>>(pos, nullptr);

    // 2) Flash attention (tensor cores, split-fp32) -> bf16 hi/lo O
    attn_mma_kernel<<<dim3(T_ / 128, HQ_, B_), 128, ATTN_SMEM_BYTES>>>();

    // 3) Output projection (tensor cores) -> fp32 out
    gemm_mma_kernel<1><<<dim3(16, (B_ * T_) / 128), 256, GEMM_SMEM_BYTES>>>(pos, out);
}

// round 15
// speedup vs baseline: 1.3922x; 1.1227x over previous
#include <cuda_runtime.h>
#include <cuda_bf16.h>
#include <cuda_fp16.h>
#include <math.h>
#include <float.h>
#include <stdint.h>

// Problem constants
#define B_    2
#define T_    2048
#define DM_   2048
#define HQ_   32
#define HKV_  8
#define HD_   64
#define LOG2_THETA 13.287712379549449
#define LOG2E_F 1.4426950408889634f

// Scratch (no allocs -> __device__ globals)
__device__ __nv_bfloat16 g_xhi[(size_t)4096 * 2048];
__device__ __nv_bfloat16 g_xlo[(size_t)4096 * 2048];
__device__ __nv_bfloat16 g_Whi[(size_t)3072 * 2048];   // WQ|WK|WV rows (bf16 hi/lo)
__device__ __nv_bfloat16 g_Wlo[(size_t)3072 * 2048];
__device__ __half        g_WOh16[(size_t)2048 * 2048]; // WO fp16 hi/lo
__device__ __half        g_WOl16[(size_t)2048 * 2048];
__device__ __nv_bfloat16 g_Qhi[(size_t)B_ * HQ_  * T_ * HD_];  // rope'd, scaled 0.125*log2e
__device__ __nv_bfloat16 g_Qlo[(size_t)B_ * HQ_  * T_ * HD_];
__device__ __nv_bfloat16 g_Khi[(size_t)B_ * HKV_ * T_ * HD_];  // rope'd
__device__ __nv_bfloat16 g_Klo[(size_t)B_ * HKV_ * T_ * HD_];
__device__ __half        g_Vh16[(size_t)B_ * HKV_ * T_ * HD_]; // V fp16 hi/lo
__device__ __half        g_Vl16[(size_t)B_ * HKV_ * T_ * HD_];
__device__ __half        g_Of16[(size_t)B_ * T_ * DM_];        // attention out, fp16

// ============================================================================
// PTX helpers (legacy tensor path: plain PTX, valid on compute_103)
// ============================================================================
__device__ __forceinline__ uint32_t smem_u32(const void* p) {
    uint32_t a;
    asm("{ .reg .u64 t; cvta.to.shared.u64 t, %1; cvt.u32.u64 %0, t; }"
        : "=r"(a) : "l"(p));
    return a;
}
__device__ __forceinline__ void ldsm_x4(uint32_t& r0, uint32_t& r1,
                                        uint32_t& r2, uint32_t& r3, uint32_t a) {
    asm volatile("ldmatrix.sync.aligned.m8n8.x4.shared.b16 {%0,%1,%2,%3}, [%4];"
                 : "=r"(r0), "=r"(r1), "=r"(r2), "=r"(r3) : "r"(a));
}
__device__ __forceinline__ void ldsm_x4_t(uint32_t& r0, uint32_t& r1,
                                          uint32_t& r2, uint32_t& r3, uint32_t a) {
    asm volatile("ldmatrix.sync.aligned.m8n8.x4.trans.shared.b16 {%0,%1,%2,%3}, [%4];"
                 : "=r"(r0), "=r"(r1), "=r"(r2), "=r"(r3) : "r"(a));
}
__device__ __forceinline__ void mma16816(float* d, const uint32_t* a, const uint32_t* b) {
    asm volatile(
        "mma.sync.aligned.m16n8k16.row.col.f32.bf16.bf16.f32 "
        "{%0,%1,%2,%3}, {%4,%5,%6,%7}, {%8,%9}, {%0,%1,%2,%3};"
        : "+f"(d[0]), "+f"(d[1]), "+f"(d[2]), "+f"(d[3])
        : "r"(a[0]), "r"(a[1]), "r"(a[2]), "r"(a[3]), "r"(b[0]), "r"(b[1]));
}
__device__ __forceinline__ void mma16816h(float* d, const uint32_t* a, const uint32_t* b) {
    asm volatile(
        "mma.sync.aligned.m16n8k16.row.col.f32.f16.f16.f32 "
        "{%0,%1,%2,%3}, {%4,%5,%6,%7}, {%8,%9}, {%0,%1,%2,%3};"
        : "+f"(d[0]), "+f"(d[1]), "+f"(d[2]), "+f"(d[3])
        : "r"(a[0]), "r"(a[1]), "r"(a[2]), "r"(a[3]), "r"(b[0]), "r"(b[1]));
}
__device__ __forceinline__ float ex2f(float x) {
    float r;
    asm("ex2.approx.f32 %0, %1;" : "=f"(r) : "f"(x));
    return r;
}
__device__ __forceinline__ void split1(float v, __nv_bfloat16& h, __nv_bfloat16& l) {
    h = __float2bfloat16_rn(v);
    l = __float2bfloat16_rn(v - __bfloat162float(h));
}
__device__ __forceinline__ uint32_t pack_hl(float a, float b, uint32_t& lo) {
    __nv_bfloat16 ha, hb, la, lb;
    split1(a, ha, la);
    split1(b, hb, lb);
    lo = (uint32_t)__bfloat16_as_ushort(la) | ((uint32_t)__bfloat16_as_ushort(lb) << 16);
    return (uint32_t)__bfloat16_as_ushort(ha) | ((uint32_t)__bfloat16_as_ushort(hb) << 16);
}
// fp16 hi/lo pack of a float pair
__device__ __forceinline__ uint32_t pack_hl_h(float a, float b, uint32_t& lo) {
    __half ha = __float2half_rn(a), hb = __float2half_rn(b);
    __half la = __float2half_rn(a - __half2float(ha));
    __half lb = __float2half_rn(b - __half2float(hb));
    lo = (uint32_t)__half_as_ushort(la) | ((uint32_t)__half_as_ushort(lb) << 16);
    return (uint32_t)__half_as_ushort(ha) | ((uint32_t)__half_as_ushort(hb) << 16);
}
__device__ __forceinline__ uint32_t f16x2(float a, float b) {
    __half2 h = __floats2half2_rn(a, b);   // .x = a (low), .y = b (high)
    return *reinterpret_cast<uint32_t*>(&h);
}

// ============================================================================
// Kernel 0: fp32 -> hi/lo conversion. x, WQ|WK|WV -> bf16; WO -> fp16.
// ============================================================================
#define NE_X   8388608ull
#define NE_WQ  4194304ull
#define NE_WKV 1048576ull
#define CVT_TOTAL_F4 4718592

__global__ __launch_bounds__(256)
void cvt_kernel(const float* __restrict__ x,  const float* __restrict__ WQ,
                const float* __restrict__ WK, const float* __restrict__ WV,
                const float* __restrict__ WO)
{
    const size_t e = ((size_t)blockIdx.x * 256 + threadIdx.x) * 4;
    if (e >= NE_X + NE_WQ + 2 * NE_WKV) {                 // WO -> fp16 hi/lo
        const size_t off = e - NE_X - NE_WQ - 2 * NE_WKV;
        float4 v = *(const float4*)(WO + off);
        uint2 uh, ul;
        uh.x = pack_hl_h(v.x, v.y, ul.x);
        uh.y = pack_hl_h(v.z, v.w, ul.y);
        *(uint2*)(g_WOh16 + off) = uh;
        *(uint2*)(g_WOl16 + off) = ul;
        return;
    }
    const float* src; __nv_bfloat16 *dh, *dl; size_t off;
    if (e < NE_X)                       { src = x;  dh = g_xhi;           dl = g_xlo;           off = e; }
    else if (e < NE_X + NE_WQ)          { src = WQ; dh = g_Whi;           dl = g_Wlo;           off = e - NE_X; }
    else if (e < NE_X + NE_WQ + NE_WKV) { src = WK; dh = g_Whi + 4194304; dl = g_Wlo + 4194304; off = e - NE_X - NE_WQ; }
    else                                { src = WV; dh = g_Whi + 5242880; dl = g_Wlo + 5242880; off = e - NE_X - NE_WQ - NE_WKV; }
    float4 v = *(const float4*)(src + off);
    uint2 uh, ul;
    uh.x = pack_hl(v.x, v.y, ul.x);
    uh.y = pack_hl(v.z, v.w, ul.y);
    *(uint2*)(dh + off) = uh;
    *(uint2*)(dl + off) = ul;
}

// ============================================================================
// QKV projection GEMM (R8-exact mainloop, bf16 3-pass): D[128x128] = x * W^T.
// Epilogue: RoPE -> bf16 hi/lo Q (scaled 0.125*log2e) / K; V -> fp16 hi/lo.
// ============================================================================
#define SPAD 40

__global__ __launch_bounds__(256)
void gemm_qkv_kernel(const int* __restrict__ pos)
{
    __shared__ __align__(16) __nv_bfloat16 sA[2][128 * SPAD];
    __shared__ __align__(16) __nv_bfloat16 sB[2][128 * SPAD];

    const int j0 = blockIdx.x * 128;
    const int m0 = blockIdx.y * 128;
    const int tid = threadIdx.x;
    const int wid = tid >> 5, lane = tid & 31;

    const __nv_bfloat16* Ahi = g_xhi;
    const __nv_bfloat16* Alo = g_xlo;
    const __nv_bfloat16* Bhi = g_Whi + (size_t)j0 * DM_;
    const __nv_bfloat16* Blo = g_Wlo + (size_t)j0 * DM_;

    const int lrow = tid >> 1;
    const int lcol = (tid & 1) * 16;
    const size_t aoff = (size_t)(m0 + lrow) * DM_ + lcol;
    const size_t boff = (size_t)lrow * DM_ + lcol;

    const int wm = (wid & 3) * 32;
    const int wn = (wid >> 2) * 64;

    float acc[2][8][4];
#pragma unroll
    for (int mt = 0; mt < 2; mt++)
#pragma unroll
        for (int nt = 0; nt < 8; nt++)
#pragma unroll
            for (int q = 0; q < 4; q++) acc[mt][nt][q] = 0.f;

    const uint32_t aB = smem_u32(sA);
    const uint32_t bB = smem_u32(sB);
    const int sidx = lrow * SPAD + lcol;

    uint4 pa0 = *(const uint4*)(Ahi + aoff);
    uint4 pa1 = *(const uint4*)(Ahi + aoff + 8);
    uint4 pa2 = *(const uint4*)(Alo + aoff);
    uint4 pa3 = *(const uint4*)(Alo + aoff + 8);
    uint4 pb0 = *(const uint4*)(Bhi + boff);
    uint4 pb1 = *(const uint4*)(Bhi + boff + 8);
    uint4 pb2 = *(const uint4*)(Blo + boff);
    uint4 pb3 = *(const uint4*)(Blo + boff + 8);

    for (int kc = 0; kc < DM_ / 32; kc++) {
        __syncthreads();
        *(uint4*)&sA[0][sidx]     = pa0;
        *(uint4*)&sA[0][sidx + 8] = pa1;
        *(uint4*)&sA[1][sidx]     = pa2;
        *(uint4*)&sA[1][sidx + 8] = pa3;
        *(uint4*)&sB[0][sidx]     = pb0;
        *(uint4*)&sB[0][sidx + 8] = pb1;
        *(uint4*)&sB[1][sidx]     = pb2;
        *(uint4*)&sB[1][sidx + 8] = pb3;
        __syncthreads();

        if (kc + 1 < DM_ / 32) {
            const size_t nk = (size_t)(kc + 1) * 32;
            pa0 = *(const uint4*)(Ahi + aoff + nk);
            pa1 = *(const uint4*)(Ahi + aoff + nk + 8);
            pa2 = *(const uint4*)(Alo + aoff + nk);
            pa3 = *(const uint4*)(Alo + aoff + nk + 8);
            pb0 = *(const uint4*)(Bhi + boff + nk);
            pb1 = *(const uint4*)(Bhi + boff + nk + 8);
            pb2 = *(const uint4*)(Blo + boff + nk);
            pb3 = *(const uint4*)(Blo + boff + nk + 8);
        }

#pragma unroll
        for (int ks = 0; ks < 2; ks++) {
            uint32_t bh[8][2], bl[8][2];
            const int brow = wn + ((lane >> 4) & 1) * 8 + (lane & 7);
            const int bcol = ks * 16 + ((lane >> 3) & 1) * 8;
#pragma unroll
            for (int p = 0; p < 4; p++) {
                const uint32_t off = (uint32_t)((brow + p * 16) * SPAD + bcol) * 2u;
                ldsm_x4(bh[2*p][0], bh[2*p][1], bh[2*p+1][0], bh[2*p+1][1], bB + off);
                ldsm_x4(bl[2*p][0], bl[2*p][1], bl[2*p+1][0], bl[2*p+1][1],
                        bB + 128 * SPAD * 2 + off);
            }
            const int arow = wm + (lane & 15);
            const int acol = ks * 16 + (lane >> 4) * 8;
#pragma unroll
            for (int mt = 0; mt < 2; mt++) {
                uint32_t ah[4], al[4];
                const uint32_t off = (uint32_t)((arow + mt * 16) * SPAD + acol) * 2u;
                ldsm_x4(ah[0], ah[1], ah[2], ah[3], aB + off);
                ldsm_x4(al[0], al[1], al[2], al[3], aB + 128 * SPAD * 2 + off);
#pragma unroll
                for (int nt = 0; nt < 8; nt++) mma16816(acc[mt][nt], ah, bh[nt]);
#pragma unroll
                for (int nt = 0; nt < 8; nt++) mma16816(acc[mt][nt], ah, bl[nt]);
#pragma unroll
                for (int nt = 0; nt < 8; nt++) mma16816(acc[mt][nt], al, bh[nt]);
            }
        }
    }

    // ---- Epilogue: scatter Q/K (RoPE, bf16 hi/lo) or V (fp16 hi/lo) ----
    const int cpair = 2 * (lane & 3);
    const int jb = j0 + wn;
    const bool isV = (jb >= 2560);
    const bool isQ = (jb < 2048);
    const int head = isQ ? (jb >> 6) : (jb < 2560 ? ((jb - 2048) >> 6) : ((jb - 2560) >> 6));
    double invf[8];
    if (!isV) {
#pragma unroll
        for (int nt = 0; nt < 8; nt++) {
            const int pi = nt * 4 + (lane & 3);
            invf[nt] = exp2(-(2.0 * pi) * (LOG2_THETA / 64.0));
        }
    }
#pragma unroll
    for (int mt = 0; mt < 2; mt++)
#pragma unroll
        for (int half = 0; half < 2; half++) {
            const int m = m0 + wm + mt * 16 + (lane >> 2) + half * 8;
            const int bb = m >> 11;
            const int t  = m & (T_ - 1);
            if (isV) {
                const size_t doff = (((size_t)bb * HKV_ + head) * T_ + t) * HD_ + cpair;
#pragma unroll
                for (int nt = 0; nt < 8; nt++) {
                    uint32_t lo;
                    uint32_t hi = pack_hl_h(acc[mt][nt][2 * half],
                                            acc[mt][nt][2 * half + 1], lo);
                    *(uint32_t*)(g_Vh16 + doff + nt * 8) = hi;
                    *(uint32_t*)(g_Vl16 + doff + nt * 8) = lo;
                }
            } else {
                const int p = pos[t];
                const float qs = isQ ? (0.125f * LOG2E_F) : 1.0f;
                const size_t doff = isQ
                    ? (((size_t)bb * HQ_  + head) * T_ + t) * HD_ + cpair
                    : (((size_t)bb * HKV_ + head) * T_ + t) * HD_ + cpair;
                __nv_bfloat16* dsth = isQ ? g_Qhi : g_Khi;
                __nv_bfloat16* dstl = isQ ? g_Qlo : g_Klo;
#pragma unroll
                for (int nt = 0; nt < 8; nt++) {
                    double sn, cs;
                    sincos((double)p * invf[nt], &sn, &cs);
                    const float fc = (float)cs, fs = (float)sn;
                    const float fe = acc[mt][nt][2 * half];
                    const float fo = acc[mt][nt][2 * half + 1];
                    uint32_t lo;
                    uint32_t hi = pack_hl((fe * fc - fo * fs) * qs,
                                          (fe * fs + fo * fc) * qs, lo);
                    *(uint32_t*)(dsth + doff + nt * 8) = hi;
                    *(uint32_t*)(dstl + doff + nt * 8) = lo;
                }
            }
        }
}

// ============================================================================
// Out-projection GEMM, fp16 2-pass: out[m][n] = O_f16[m] . (WOhi + WOlo)[n].
// R8-style single-buffered smem, register prefetch, 2 barriers per chunk.
// ============================================================================
__global__ __launch_bounds__(256)
void gemm_out_kernel(float* __restrict__ outp)
{
    __shared__ __align__(16) __half sA[128 * SPAD];
    __shared__ __align__(16) __half sBh[128 * SPAD];
    __shared__ __align__(16) __half sBl[128 * SPAD];

    const int j0 = blockIdx.x * 128;
    const int m0 = blockIdx.y * 128;
    const int tid = threadIdx.x;
    const int wid = tid >> 5, lane = tid & 31;

    const __half* A  = g_Of16;
    const __half* Bh = g_WOh16 + (size_t)j0 * DM_;
    const __half* Bl = g_WOl16 + (size_t)j0 * DM_;

    const int lrow = tid >> 1;
    const int lcol = (tid & 1) * 16;
    const size_t aoff = (size_t)(m0 + lrow) * DM_ + lcol;
    const size_t boff = (size_t)lrow * DM_ + lcol;

    const int wm = (wid & 3) * 32;
    const int wn = (wid >> 2) * 64;

    float acc[2][8][4];
#pragma unroll
    for (int mt = 0; mt < 2; mt++)
#pragma unroll
        for (int nt = 0; nt < 8; nt++)
#pragma unroll
            for (int q = 0; q < 4; q++) acc[mt][nt][q] = 0.f;

    const uint32_t aB  = smem_u32(sA);
    const uint32_t bhB = smem_u32(sBh);
    const uint32_t blB = smem_u32(sBl);
    const int sidx = lrow * SPAD + lcol;

    uint4 pa0 = *(const uint4*)(A + aoff);
    uint4 pa1 = *(const uint4*)(A + aoff + 8);
    uint4 pb0 = *(const uint4*)(Bh + boff);
    uint4 pb1 = *(const uint4*)(Bh + boff + 8);
    uint4 pb2 = *(const uint4*)(Bl + boff);
    uint4 pb3 = *(const uint4*)(Bl + boff + 8);

    for (int kc = 0; kc < DM_ / 32; kc++) {
        __syncthreads();
        *(uint4*)&sA[sidx]      = pa0;
        *(uint4*)&sA[sidx + 8]  = pa1;
        *(uint4*)&sBh[sidx]     = pb0;
        *(uint4*)&sBh[sidx + 8] = pb1;
        *(uint4*)&sBl[sidx]     = pb2;
        *(uint4*)&sBl[sidx + 8] = pb3;
        __syncthreads();

        if (kc + 1 < DM_ / 32) {
            const size_t nk = (size_t)(kc + 1) * 32;
            pa0 = *(const uint4*)(A + aoff + nk);
            pa1 = *(const uint4*)(A + aoff + nk + 8);
            pb0 = *(const uint4*)(Bh + boff + nk);
            pb1 = *(const uint4*)(Bh + boff + nk + 8);
            pb2 = *(const uint4*)(Bl + boff + nk);
            pb3 = *(const uint4*)(Bl + boff + nk + 8);
        }

#pragma unroll
        for (int ks = 0; ks < 2; ks++) {
            uint32_t bh[8][2], bl[8][2];
            const int brow = wn + ((lane >> 4) & 1) * 8 + (lane & 7);
            const int bcol = ks * 16 + ((lane >> 3) & 1) * 8;
#pragma unroll
            for (int p = 0; p < 4; p++) {
                const uint32_t off = (uint32_t)((brow + p * 16) * SPAD + bcol) * 2u;
                ldsm_x4(bh[2*p][0], bh[2*p][1], bh[2*p+1][0], bh[2*p+1][1], bhB + off);
                ldsm_x4(bl[2*p][0], bl[2*p][1], bl[2*p+1][0], bl[2*p+1][1], blB + off);
            }
            const int arow = wm + (lane & 15);
            const int acol = ks * 16 + (lane >> 4) * 8;
#pragma unroll
            for (int mt = 0; mt < 2; mt++) {
                uint32_t ah[4];
                const uint32_t off = (uint32_t)((arow + mt * 16) * SPAD + acol) * 2u;
                ldsm_x4(ah[0], ah[1], ah[2], ah[3], aB + off);
#pragma unroll
                for (int nt = 0; nt < 8; nt++) mma16816h(acc[mt][nt], ah, bh[nt]);
#pragma unroll
                for (int nt = 0; nt < 8; nt++) mma16816h(acc[mt][nt], ah, bl[nt]);
            }
        }
    }

    const int cpair = 2 * (lane & 3);
#pragma unroll
    for (int mt = 0; mt < 2; mt++)
#pragma unroll
        for (int half = 0; half < 2; half++) {
            const int m = m0 + wm + mt * 16 + (lane >> 2) + half * 8;
            float* dst = outp + (size_t)m * DM_ + j0 + wn + cpair;
#pragma unroll
            for (int nt = 0; nt < 8; nt++)
                *(float2*)(dst + nt * 8) =
                    make_float2(acc[mt][nt][2 * half], acc[mt][nt][2 * half + 1]);
        }
}

// ============================================================================
// Causal GQA flash attention (R8-exact structure).
// S = QK^T: bf16 3-pass. PV: fp16 2-pass (P fp16, V fp16 hi/lo).
// Softmax in log2-space (Q pre-scaled by 0.125*log2e; ex2.approx).
// 72 KB dyn smem -> 2 CTAs/SM.
// ============================================================================
#define APAD 72
#define ATTN_SMEM_BYTES ((128 * APAD * 2 + 64 * APAD * 4) * 2)

__global__ __launch_bounds__(128, 2)
void attn_mma_kernel()
{
    extern __shared__ __align__(16) char smraw[];
    __nv_bfloat16* Qh = (__nv_bfloat16*)smraw;          // [128][APAD]
    __nv_bfloat16* Ql = Qh + 128 * APAD;
    __nv_bfloat16* Kh = Ql + 128 * APAD;                // [64][APAD]
    __nv_bfloat16* Kl = Kh + 64 * APAD;
    __half*        Vh = (__half*)(Kl + 64 * APAD);      // [64][APAD] fp16
    __half*        Vl = Vh + 64 * APAD;

    const int qt = (int)gridDim.x - 1 - (int)blockIdx.x;
    const int hq = blockIdx.y;
    const int bb = blockIdx.z;
    const int hk = hq >> 2;

    const int tid = threadIdx.x;
    const int wid = tid >> 5, lane = tid & 31;
    const int wm = wid * 32;
    const int gID = lane >> 2, tig = lane & 3;

    const uint32_t QhB = smem_u32(Qh), QlB = smem_u32(Ql);
    const uint32_t KhB = smem_u32(Kh), KlB = smem_u32(Kl);
    const uint32_t VhB = smem_u32(Vh), VlB = smem_u32(Vl);

    // Load Q tile (hi/lo): one 64-elem row per thread
    {
        const size_t qoff = (((size_t)bb * HQ_ + hq) * T_ + (size_t)qt * 128 + tid) * HD_;
#pragma unroll
        for (int v = 0; v < 8; v++) {
            *(uint4*)&Qh[tid * APAD + v * 8] = *(const uint4*)(g_Qhi + qoff + v * 8);
            *(uint4*)&Ql[tid * APAD + v * 8] = *(const uint4*)(g_Qlo + qoff + v * 8);
        }
    }

    float O[2][8][4];
#pragma unroll
    for (int mt = 0; mt < 2; mt++)
#pragma unroll
        for (int nt = 0; nt < 8; nt++)
#pragma unroll
            for (int q = 0; q < 4; q++) O[mt][nt][q] = 0.f;
    float m_st[2][2], l_st[2][2];
#pragma unroll
    for (int mt = 0; mt < 2; mt++)
#pragma unroll
        for (int h2 = 0; h2 < 2; h2++) { m_st[mt][h2] = -FLT_MAX; l_st[mt][h2] = 0.f; }

    const size_t kvbase = ((size_t)bb * HKV_ + hk) * T_ * HD_;
    const int lrow = tid >> 1;
    const int lhalf = (tid & 1) * 32;
    const int ktmax = 2 * qt + 1;

    for (int kt = 0; kt <= ktmax; kt++) {
        __syncthreads();
        {
            const size_t goff = kvbase + ((size_t)kt * 64 + lrow) * HD_ + lhalf;
            const int soff = lrow * APAD + lhalf;
#pragma unroll
            for (int v = 0; v < 4; v++) {
                *(uint4*)&Kh[soff + v * 8] = *(const uint4*)(g_Khi + goff + v * 8);
                *(uint4*)&Kl[soff + v * 8] = *(const uint4*)(g_Klo + goff + v * 8);
                *(uint4*)&Vh[soff + v * 8] = *(const uint4*)(g_Vh16 + goff + v * 8);
                *(uint4*)&Vl[soff + v * 8] = *(const uint4*)(g_Vl16 + goff + v * 8);
            }
        }
        __syncthreads();

        // ---- S = Q K^T (3 passes, bf16) ----
        float S[2][8][4];
#pragma unroll
        for (int mt = 0; mt < 2; mt++)
#pragma unroll
            for (int nt = 0; nt < 8; nt++)
#pragma unroll
                for (int q = 0; q < 4; q++) S[mt][nt][q] = 0.f;

#pragma unroll
        for (int ks = 0; ks < 4; ks++) {
            uint32_t bh[8][2], bl[8][2];
            const int brow = ((lane >> 4) & 1) * 8 + (lane & 7);
            const int bcol = ks * 16 + ((lane >> 3) & 1) * 8;
#pragma unroll
            for (int p = 0; p < 4; p++) {
                const uint32_t off = (uint32_t)((brow + p * 16) * APAD + bcol) * 2u;
                ldsm_x4(bh[2*p][0], bh[2*p][1], bh[2*p+1][0], bh[2*p+1][1], KhB + off);
                ldsm_x4(bl[2*p][0], bl[2*p][1], bl[2*p+1][0], bl[2*p+1][1], KlB + off);
            }
            const int arow = wm + (lane & 15);
            const int acol = ks * 16 + (lane >> 4) * 8;
#pragma unroll
            for (int mt = 0; mt < 2; mt++) {
                uint32_t ah[4], al[4];
                const uint32_t off = (uint32_t)((arow + mt * 16) * APAD + acol) * 2u;
                ldsm_x4(ah[0], ah[1], ah[2], ah[3], QhB + off);
                ldsm_x4(al[0], al[1], al[2], al[3], QlB + off);
#pragma unroll
                for (int nt = 0; nt < 8; nt++) mma16816(S[mt][nt], ah, bh[nt]);
#pragma unroll
                for (int nt = 0; nt < 8; nt++) mma16816(S[mt][nt], ah, bl[nt]);
#pragma unroll
                for (int nt = 0; nt < 8; nt++) mma16816(S[mt][nt], al, bh[nt]);
            }
        }

        // ---- Causal mask (diagonal tiles only) ----
        if (kt >= 2 * qt) {
            const int rg = qt * 128 + wm + gID;
            const int cg = kt * 64 + 2 * tig;
#pragma unroll
            for (int mt = 0; mt < 2; mt++)
#pragma unroll
                for (int nt = 0; nt < 8; nt++)
#pragma unroll
                    for (int h2 = 0; h2 < 2; h2++)
#pragma unroll
                        for (int e = 0; e < 2; e++)
                            if (cg + nt * 8 + e > rg + mt * 16 + h2 * 8)
                                S[mt][nt][2 * h2 + e] = -FLT_MAX;
        }

        // ---- Online softmax in log2-space (quad rows; shfl_xor 1,2) ----
#pragma unroll
        for (int mt = 0; mt < 2; mt++)
#pragma unroll
            for (int h2 = 0; h2 < 2; h2++) {
                float mx = -FLT_MAX;
#pragma unroll
                for (int nt = 0; nt < 8; nt++)
                    mx = fmaxf(mx, fmaxf(S[mt][nt][2 * h2], S[mt][nt][2 * h2 + 1]));
                mx = fmaxf(mx, __shfl_xor_sync(0xffffffffu, mx, 1));
                mx = fmaxf(mx, __shfl_xor_sync(0xffffffffu, mx, 2));
                const float nm = fmaxf(m_st[mt][h2], mx);
                float sum = 0.f;
#pragma unroll
                for (int nt = 0; nt < 8; nt++) {
                    S[mt][nt][2 * h2]     = ex2f(S[mt][nt][2 * h2]     - nm);
                    S[mt][nt][2 * h2 + 1] = ex2f(S[mt][nt][2 * h2 + 1] - nm);
                    sum += S[mt][nt][2 * h2] + S[mt][nt][2 * h2 + 1];
                }
                sum += __shfl_xor_sync(0xffffffffu, sum, 1);
                sum += __shfl_xor_sync(0xffffffffu, sum, 2);
                const float corr = ex2f(m_st[mt][h2] - nm);
                m_st[mt][h2] = nm;
                l_st[mt][h2] = l_st[mt][h2] * corr + sum;
#pragma unroll
                for (int nt = 0; nt < 8; nt++) {
                    O[mt][nt][2 * h2]     *= corr;
                    O[mt][nt][2 * h2 + 1] *= corr;
                }
            }

        // ---- O += P V (fp16, 2 passes; P packed register-locally) ----
#pragma unroll
        for (int ks = 0; ks < 4; ks++) {
            uint32_t vh[8][2], vl[8][2];
            const int vrow = ks * 16 + (lane & 15);
#pragma unroll
            for (int p = 0; p < 4; p++) {
                const uint32_t off =
                    (uint32_t)(vrow * APAD + p * 16 + (lane >> 4) * 8) * 2u;
                ldsm_x4_t(vh[2*p][0], vh[2*p][1], vh[2*p+1][0], vh[2*p+1][1], VhB + off);
                ldsm_x4_t(vl[2*p][0], vl[2*p][1], vl[2*p+1][0], vl[2*p+1][1], VlB + off);
            }
#pragma unroll
            for (int mt = 0; mt < 2; mt++) {
                uint32_t ph[4];
                ph[0] = f16x2(S[mt][2*ks][0],   S[mt][2*ks][1]);
                ph[1] = f16x2(S[mt][2*ks][2],   S[mt][2*ks][3]);
                ph[2] = f16x2(S[mt][2*ks+1][0], S[mt][2*ks+1][1]);
                ph[3] = f16x2(S[mt][2*ks+1][2], S[mt][2*ks+1][3]);
#pragma unroll
                for (int nt = 0; nt < 8; nt++) mma16816h(O[mt][nt], ph, vh[nt]);
#pragma unroll
                for (int nt = 0; nt < 8; nt++) mma16816h(O[mt][nt], ph, vl[nt]);
            }
        }
    }

    // ---- Finalize: /l, store fp16 O for the out-projection ----
#pragma unroll
    for (int mt = 0; mt < 2; mt++)
#pragma unroll
        for (int h2 = 0; h2 < 2; h2++) {
            const float inv = 1.0f / l_st[mt][h2];
            const int rg = qt * 128 + wm + mt * 16 + gID + h2 * 8;
            const size_t off = ((size_t)bb * T_ + rg) * DM_ + hq * HD_ + 2 * tig;
#pragma unroll
            for (int nt = 0; nt < 8; nt++)
                *(uint32_t*)(g_Of16 + off + nt * 8) =
                    f16x2(O[mt][nt][2 * h2] * inv, O[mt][nt][2 * h2 + 1] * inv);
        }
}

// ============================================================================
extern "C" void kernel_launch(void* const* d_in, const int* in_sizes, int n_in,
                              void* d_out, int out_size)
{
    const float* x   = (const float*)d_in[0];
    const int*   pos = (const int*)  d_in[1];
    const float* WQ  = (const float*)d_in[2];
    const float* WK  = (const float*)d_in[3];
    const float* WV  = (const float*)d_in[4];
    const float* WO  = (const float*)d_in[5];
    float* out = (float*)d_out;

    cudaFuncSetAttribute(attn_mma_kernel, cudaFuncAttributeMaxDynamicSharedMemorySize,
                         ATTN_SMEM_BYTES);

    // 0) hi/lo conversion (x, W -> bf16; WO -> fp16)
    cvt_kernel<<<CVT_TOTAL_F4 / 256, 256>>>(x, WQ, WK, WV, WO);

    // 1) QKV projection + RoPE -> bf16 Q/K (Q scaled 0.125*log2e), fp16 V
    gemm_qkv_kernel<<<dim3(24, (B_ * T_) / 128), 256>>>(pos);

    // 2) Flash attention -> fp16 O
    attn_mma_kernel<<<dim3(T_ / 128, HQ_, B_), 128, ATTN_SMEM_BYTES>>>();

    // 3) Output projection (fp16 2-pass) -> fp32 out
    gemm_out_kernel<<<dim3(16, (B_ * T_) / 128), 256>>>(out);
}